// round 3
// baseline (speedup 1.0000x reference)
#include <cuda_runtime.h>
#include <cuda_bf16.h>
#include <math.h>

#define NB 8192
#define NC 32000

// per-row loss scratch + completion counter (device globals: allocation-free)
__device__ float g_row_loss[NB];
__device__ unsigned int g_done_count = 0;

__inline__ __device__ float warpReduceSum(float v) {
#pragma unroll
    for (int o = 16; o > 0; o >>= 1)
        v += __shfl_down_sync(0xffffffffu, v, o);
    return v;
}

__inline__ __device__ double warpReduceSumD(double v) {
#pragma unroll
    for (int o = 16; o > 0; o >>= 1)
        v += __shfl_down_sync(0xffffffffu, v, o);
    return v;
}

__global__ __launch_bounds__(256) void row_loss_kernel(
    const float* __restrict__ y_pred,
    const int* __restrict__ y_true,   // JAX x64-disabled: int64 degrades to int32
    float* __restrict__ out)
{
    const int row = blockIdx.x;
    const float* rowp = y_pred + (size_t)row * NC;
    const float4* p4 = reinterpret_cast<const float4*>(rowp);
    const int n4 = NC / 4;  // 8000

    float s = 0.0f;
#pragma unroll 8
    for (int i = threadIdx.x; i < n4; i += 256) {
        float4 v = __ldg(p4 + i);
        s += __expf(v.x) + __expf(v.y) + __expf(v.z) + __expf(v.w);
    }

    // block reduce (fp32)
    __shared__ float sh[8];
    const int lane = threadIdx.x & 31;
    const int wid  = threadIdx.x >> 5;
    s = warpReduceSum(s);
    if (lane == 0) sh[wid] = s;
    __syncthreads();
    if (threadIdx.x == 0) {
        float v = 0.0f;
#pragma unroll
        for (int w = 0; w < 8; w++) v += sh[w];
        int t = y_true[row];
        t = (t < 0) ? 0 : ((t >= NC) ? NC - 1 : t);   // crash guard
        const float pt = __ldg(rowp + t);
        const float et = __expf(pt);
        const float sneg = v - et;                    // sum over negatives
        g_row_loss[row] = log1pf(sneg * __expf(-pt));
    }

    // ---- last-block-done fused mean ----
    __shared__ bool isLast;
    __threadfence();                                  // publish g_row_loss[row]
    if (threadIdx.x == 0) {
        unsigned int c = atomicAdd(&g_done_count, 1u);
        isLast = (c == NB - 1);
    }
    __syncthreads();
    if (!isLast) return;

    // Fixed reduction tree over g_row_loss -> deterministic output
    double d = 0.0;
#pragma unroll 4
    for (int i = threadIdx.x; i < NB; i += 256)
        d += (double)g_row_loss[i];

    __shared__ double shd[8];
    d = warpReduceSumD(d);
    if (lane == 0) shd[wid] = d;
    __syncthreads();
    if (threadIdx.x == 0) {
        double v = 0.0;
#pragma unroll
        for (int w = 0; w < 8; w++) v += shd[w];
        out[0] = (float)(v / (double)NB);
        g_done_count = 0;                             // reset for next graph replay
    }
}

extern "C" void kernel_launch(void* const* d_in, const int* in_sizes, int n_in,
                              void* d_out, int out_size)
{
    const float* y_pred = (const float*)d_in[0];
    const int*   y_true = (const int*)d_in[1];
    float* out = (float*)d_out;

    row_loss_kernel<<<NB, 256>>>(y_pred, y_true, out);
}

// round 4
// speedup vs baseline: 1.0128x; 1.0128x over previous
#include <cuda_runtime.h>
#include <cuda_bf16.h>
#include <math.h>

#define NB 8192
#define NC 32000

// per-row loss scratch + completion counter (device globals: allocation-free)
__device__ float g_row_loss[NB];
__device__ unsigned int g_done_count = 0;

__inline__ __device__ float warpReduceSum(float v) {
#pragma unroll
    for (int o = 16; o > 0; o >>= 1)
        v += __shfl_down_sync(0xffffffffu, v, o);
    return v;
}

__inline__ __device__ double warpReduceSumD(double v) {
#pragma unroll
    for (int o = 16; o > 0; o >>= 1)
        v += __shfl_down_sync(0xffffffffu, v, o);
    return v;
}

__global__ __launch_bounds__(256) void row_loss_kernel(
    const float* __restrict__ y_pred,
    const int* __restrict__ y_true,   // JAX x64-disabled: int64 degrades to int32
    float* __restrict__ out)
{
    const int row = blockIdx.x;
    const float* rowp = y_pred + (size_t)row * NC;
    const float4* p4 = reinterpret_cast<const float4*>(rowp);
    const int n4 = NC / 4;  // 8000

    float s = 0.0f;
#pragma unroll 4
    for (int i = threadIdx.x; i < n4; i += 256) {
        float4 v = __ldg(p4 + i);
        s += __expf(v.x) + __expf(v.y) + __expf(v.z) + __expf(v.w);
    }

    // block reduce (fp32)
    __shared__ float sh[8];
    __shared__ bool isLast;
    const int lane = threadIdx.x & 31;
    const int wid  = threadIdx.x >> 5;
    s = warpReduceSum(s);
    if (lane == 0) sh[wid] = s;
    __syncthreads();
    if (threadIdx.x == 0) {
        float v = 0.0f;
#pragma unroll
        for (int w = 0; w < 8; w++) v += sh[w];
        int t = y_true[row];
        t = (t < 0) ? 0 : ((t >= NC) ? NC - 1 : t);   // crash guard
        const float pt = __ldg(rowp + t);
        const float et = __expf(pt);
        const float sneg = v - et;                    // sum over negatives
        g_row_loss[row] = log1pf(sneg * __expf(-pt));
        // release: publish our partial before signaling done (thread 0 only,
        // it is the sole writer -> no block-wide membar storm)
        __threadfence();
        unsigned int c = atomicAdd(&g_done_count, 1u);
        isLast = (c == NB - 1);
    }
    __syncthreads();
    if (!isLast) return;

    // Last CTA: fixed reduction tree over g_row_loss -> deterministic output.
    // __ldcg reads straight from L2 (coherence point) -> no stale-L1 hazard.
    double d = 0.0;
#pragma unroll 4
    for (int i = threadIdx.x; i < NB; i += 256)
        d += (double)__ldcg(&g_row_loss[i]);

    __shared__ double shd[8];
    d = warpReduceSumD(d);
    if (lane == 0) shd[wid] = d;
    __syncthreads();
    if (threadIdx.x == 0) {
        double v = 0.0;
#pragma unroll
        for (int w = 0; w < 8; w++) v += shd[w];
        out[0] = (float)(v / (double)NB);
        g_done_count = 0;                             // reset for next graph replay
    }
}

extern "C" void kernel_launch(void* const* d_in, const int* in_sizes, int n_in,
                              void* d_out, int out_size)
{
    const float* y_pred = (const float*)d_in[0];
    const int*   y_true = (const int*)d_in[1];
    float* out = (float*)d_out;

    row_loss_kernel<<<NB, 256>>>(y_pred, y_true, out);
}

// round 10
// speedup vs baseline: 1.0352x; 1.0222x over previous
#include <cuda_runtime.h>
#include <cuda_bf16.h>
#include <math.h>

#define NB 8192
#define NC 32000

// per-row loss scratch (device global: allocation-free)
__device__ float g_row_loss[NB];

__inline__ __device__ float warpReduceSum(float v) {
#pragma unroll
    for (int o = 16; o > 0; o >>= 1)
        v += __shfl_down_sync(0xffffffffu, v, o);
    return v;
}

__inline__ __device__ double warpReduceSumD(double v) {
#pragma unroll
    for (int o = 16; o > 0; o >>= 1)
        v += __shfl_down_sync(0xffffffffu, v, o);
    return v;
}

__global__ __launch_bounds__(256) void row_loss_kernel(
    const float* __restrict__ y_pred,
    const int* __restrict__ y_true)   // JAX x64-disabled: int64 degrades to int32
{
    const int row = blockIdx.x;
    const float* rowp = y_pred + (size_t)row * NC;
    const float4* p4 = reinterpret_cast<const float4*>(rowp);
    const int n4 = NC / 4;  // 8000

    float s = 0.0f;
#pragma unroll 4
    for (int i = threadIdx.x; i < n4; i += 256) {
        float4 v = __ldcs(p4 + i);   // read-once: evict-first, keep L2 clean
        s += __expf(v.x) + __expf(v.y) + __expf(v.z) + __expf(v.w);
    }

    // block reduce (fp32)
    __shared__ float sh[8];
    const int lane = threadIdx.x & 31;
    const int wid  = threadIdx.x >> 5;
    s = warpReduceSum(s);
    if (lane == 0) sh[wid] = s;
    __syncthreads();
    if (threadIdx.x == 0) {
        float v = 0.0f;
#pragma unroll
        for (int w = 0; w < 8; w++) v += sh[w];
        int t = y_true[row];
        t = (t < 0) ? 0 : ((t >= NC) ? NC - 1 : t);   // crash guard
        const float pt = __ldg(rowp + t);
        const float et = __expf(pt);
        const float sneg = v - et;                    // sum over negatives
        g_row_loss[row] = log1pf(sneg * __expf(-pt));
    }
}

__global__ __launch_bounds__(256) void mean_kernel(float* __restrict__ out)
{
    // PDL: block is resident early; wait here for the primary grid to fully
    // complete (no early trigger used -> completion == full grid + mem visible).
    cudaGridDependencySynchronize();

    double s = 0.0;
#pragma unroll 4
    for (int i = threadIdx.x; i < NB; i += 256)
        s += (double)g_row_loss[i];

    __shared__ double sh[8];
    const int lane = threadIdx.x & 31;
    const int wid  = threadIdx.x >> 5;
    s = warpReduceSumD(s);
    if (lane == 0) sh[wid] = s;
    __syncthreads();
    if (threadIdx.x == 0) {
        double v = 0.0;
#pragma unroll
        for (int w = 0; w < 8; w++) v += sh[w];
        out[0] = (float)(v / (double)NB);
    }
}

extern "C" void kernel_launch(void* const* d_in, const int* in_sizes, int n_in,
                              void* d_out, int out_size)
{
    const float* y_pred = (const float*)d_in[0];
    const int*   y_true = (const int*)d_in[1];
    float* out = (float*)d_out;

    row_loss_kernel<<<NB, 256>>>(y_pred, y_true);

    // Launch mean_kernel with programmatic dependent launch: overlaps its
    // launch latency with the tail of row_loss_kernel.
    cudaLaunchAttribute attrs[1];
    attrs[0].id = cudaLaunchAttributeProgrammaticStreamSerialization;
    attrs[0].val.programmaticStreamSerializationAllowed = 1;

    cudaLaunchConfig_t cfg = {};
    cfg.gridDim  = dim3(1, 1, 1);
    cfg.blockDim = dim3(256, 1, 1);
    cfg.dynamicSmemBytes = 0;
    cfg.stream = 0;
    cfg.attrs = attrs;
    cfg.numAttrs = 1;

    cudaLaunchKernelEx(&cfg, mean_kernel, out);
}

// round 11
// speedup vs baseline: 1.0782x; 1.0415x over previous
#include <cuda_runtime.h>
#include <cuda_bf16.h>
#include <math.h>

#define NB 8192
#define NC 32000

// device-global accumulator (allocation-free). Starts 0; finalize resets it
// after every call so graph replays are correct.
__device__ double g_sum = 0.0;

__inline__ __device__ float warpReduceSum(float v) {
#pragma unroll
    for (int o = 16; o > 0; o >>= 1)
        v += __shfl_down_sync(0xffffffffu, v, o);
    return v;
}

__global__ __launch_bounds__(256) void row_loss_kernel(
    const float* __restrict__ y_pred,
    const int* __restrict__ y_true)   // JAX x64-disabled: int64 degrades to int32
{
    const int row = blockIdx.x;
    const float* rowp = y_pred + (size_t)row * NC;
    const float4* p4 = reinterpret_cast<const float4*>(rowp);
    const int n4 = NC / 4;  // 8000

    float s = 0.0f;
#pragma unroll 4
    for (int i = threadIdx.x; i < n4; i += 256) {
        float4 v = __ldcs(p4 + i);   // read-once: evict-first, keep L2 clean
        s += __expf(v.x) + __expf(v.y) + __expf(v.z) + __expf(v.w);
    }

    // block reduce (fp32)
    __shared__ float sh[8];
    const int lane = threadIdx.x & 31;
    const int wid  = threadIdx.x >> 5;
    s = warpReduceSum(s);
    if (lane == 0) sh[wid] = s;
    __syncthreads();
    if (threadIdx.x == 0) {
        float v = 0.0f;
#pragma unroll
        for (int w = 0; w < 8; w++) v += sh[w];
        int t = y_true[row];
        t = (t < 0) ? 0 : ((t >= NC) ? NC - 1 : t);   // crash guard
        const float pt = __ldg(rowp + t);
        const float et = __expf(pt);
        const float sneg = v - et;                    // sum over negatives
        const float loss = log1pf(sneg * __expf(-pt));
        // fire-and-forget: REDG.ADD.F64, no return value -> no retirement wait
        atomicAdd(&g_sum, (double)loss);
    }
}

__global__ void finalize_kernel(float* __restrict__ out)
{
    // PDL: resident early; wait for primary grid full completion (memory from
    // the whole grid, including its REDs, is visible after this).
    cudaGridDependencySynchronize();
    if (threadIdx.x == 0) {
        out[0] = (float)(g_sum / (double)NB);
        g_sum = 0.0;                                  // reset for next replay
    }
}

extern "C" void kernel_launch(void* const* d_in, const int* in_sizes, int n_in,
                              void* d_out, int out_size)
{
    const float* y_pred = (const float*)d_in[0];
    const int*   y_true = (const int*)d_in[1];
    float* out = (float*)d_out;

    row_loss_kernel<<<NB, 256>>>(y_pred, y_true);

    // PDL finalize: launch overlaps the row kernel's tail.
    cudaLaunchAttribute attrs[1];
    attrs[0].id = cudaLaunchAttributeProgrammaticStreamSerialization;
    attrs[0].val.programmaticStreamSerializationAllowed = 1;

    cudaLaunchConfig_t cfg = {};
    cfg.gridDim  = dim3(1, 1, 1);
    cfg.blockDim = dim3(32, 1, 1);
    cfg.dynamicSmemBytes = 0;
    cfg.stream = 0;
    cfg.attrs = attrs;
    cfg.numAttrs = 1;

    cudaLaunchKernelEx(&cfg, finalize_kernel, out);
}